// round 5
// baseline (speedup 1.0000x reference)
#include <cuda_runtime.h>
#include <cuda_fp16.h>
#include <cstdint>

// ---------------- problem constants ----------------
static constexpr int TOKENS = 4096;
static constexpr int IN_F   = 4096;
static constexpr int OUT_F  = 11008;

static constexpr int BM = 128;
static constexpr int BN = 128;
static constexpr int BK = 64;          // 64 fp16 = 128 bytes per row (SW128 atom row)
static constexpr int STAGES = 3;

static constexpr int M_TILES = TOKENS / BM;   // 32
static constexpr int N_TILES = OUT_F / BN;    // 86
static constexpr int K_TILES = IN_F / BK;     // 64

static constexpr int TILE_BYTES = 128 * BK * 2;     // 16384 (A tile == B tile)
static constexpr int STAGE_BYTES = 2 * TILE_BYTES;  // 32768
static constexpr int SMEM_BYTES = STAGES * STAGE_BYTES; // 98304

// ---------------- device scratch (no cudaMalloc allowed) ----------------
__device__ __align__(1024) uint8_t g_xbuf[(size_t)M_TILES * K_TILES * TILE_BYTES]; // 32 MB fp16 tiles, SW128
__device__ __align__(1024) uint8_t g_wbuf[(size_t)N_TILES * K_TILES * TILE_BYTES]; // 88 MB fp16 tiles, SW128

// ---------------- helpers ----------------
__device__ __forceinline__ uint32_t smem_u32(const void* p) {
    uint32_t a;
    asm("{ .reg .u64 t; cvta.to.shared.u64 t, %1; cvt.u32.u64 %0, t; }" : "=r"(a) : "l"(p));
    return a;
}
__device__ __forceinline__ uint32_t h2u(__half2 h) { uint32_t u; __builtin_memcpy(&u, &h, 4); return u; }
__device__ __forceinline__ uint32_t swz(uint32_t off) { return off ^ ((off >> 3) & 0x70); }

__device__ __forceinline__ void cpasync16(uint32_t dst, const void* src) {
    asm volatile("cp.async.cg.shared.global [%0], [%1], 16;" :: "r"(dst), "l"(src));
}
__device__ __forceinline__ void cp_commit() { asm volatile("cp.async.commit_group;" ::: "memory"); }
__device__ __forceinline__ void cp_wait1()  { asm volatile("cp.async.wait_group 1;" ::: "memory"); }

__device__ __forceinline__ void ldsm4(uint32_t* r, uint32_t addr) {
    asm volatile("ldmatrix.sync.aligned.m8n8.x4.shared.b16 {%0,%1,%2,%3}, [%4];"
                 : "=r"(r[0]), "=r"(r[1]), "=r"(r[2]), "=r"(r[3]) : "r"(addr) : "memory");
}
__device__ __forceinline__ void mma16816(float* c, const uint32_t* a, const uint32_t* b) {
    asm volatile(
        "mma.sync.aligned.m16n8k16.row.col.f32.f16.f16.f32 "
        "{%0,%1,%2,%3}, {%4,%5,%6,%7}, {%8,%9}, {%0,%1,%2,%3};"
        : "+f"(c[0]), "+f"(c[1]), "+f"(c[2]), "+f"(c[3])
        : "r"(a[0]), "r"(a[1]), "r"(a[2]), "r"(a[3]), "r"(b[0]), "r"(b[1]));
}

// ---------------- prep kernel 1: x fp32 -> fp16, tiled + SW128 ----------------
__global__ void convert_x_kernel(const float* __restrict__ x) {
    int mt = blockIdx.x / K_TILES;
    int kt = blockIdx.x % K_TILES;
    int r  = threadIdx.x; // 0..127 = M row within tile
    const float4* src = (const float4*)(x + (size_t)(mt * BM + r) * IN_F + kt * BK);
    uint8_t* dst = g_xbuf + (size_t)blockIdx.x * TILE_BYTES;
#pragma unroll
    for (int g = 0; g < 8; g++) {
        float4 a = src[2 * g];
        float4 b = src[2 * g + 1];
        uint4 v;
        v.x = h2u(__floats2half2_rn(a.x, a.y));
        v.y = h2u(__floats2half2_rn(a.z, a.w));
        v.z = h2u(__floats2half2_rn(b.x, b.y));
        v.w = h2u(__floats2half2_rn(b.z, b.w));
        uint32_t off = (uint32_t)(r * 128 + g * 16);
        *(uint4*)(dst + swz(off)) = v;
    }
}

// ---------------- prep kernel 2: int4 (as int32 per packed byte) -> fp16 dequant W ----------------
// Harness promotes uint8 weight_packed to int32: one int element per original byte.
// w[o][2i]   = ((e_i & 15)  - zero[o]) * scale[o]
// w[o][2i+1] = ((e_i >> 4)  - zero[o]) * scale[o]
__global__ void dequant_w_kernel(const int* __restrict__ wp,
                                 const float* __restrict__ scale,
                                 const float* __restrict__ zero) {
    int nt = blockIdx.x / K_TILES;
    int kt = blockIdx.x % K_TILES;
    int r  = threadIdx.x; // 0..127 = N row within tile
    int row = nt * BN + r;
    float s = scale[row];
    float b = -zero[row] * s;
    const uint4* src = (const uint4*)(wp + (size_t)row * (IN_F / 2) + kt * (BK / 2)); // 32 ints
    uint8_t* dst = g_wbuf + (size_t)blockIdx.x * TILE_BYTES;
#pragma unroll
    for (int j = 0; j < 8; j++) {
        uint4 q = src[j];                 // 4 packed-byte values -> 8 nibbles -> 8 halves = 16 bytes
        uint32_t e[4] = {q.x, q.y, q.z, q.w};
        uint32_t h[4];
#pragma unroll
        for (int t = 0; t < 4; t++) {
            float v0 = fmaf((float)(e[t] & 15u), s, b);          // even k
            float v1 = fmaf((float)((e[t] >> 4) & 15u), s, b);   // odd k
            h[t] = h2u(__floats2half2_rn(v0, v1));
        }
        uint4 v = make_uint4(h[0], h[1], h[2], h[3]);
        uint32_t off = (uint32_t)(r * 128 + j * 16);
        *(uint4*)(dst + swz(off)) = v;
    }
}

// ---------------- main GEMM: mma.sync (HMMA) + cp.async 3-stage pipeline ----------------
// 256 threads = 8 warps in a 4(M) x 2(N) grid; warp tile 32x64.
__global__ void __launch_bounds__(256, 2) gemm_kernel(float* __restrict__ out) {
    extern __shared__ __align__(1024) uint8_t sm[];
    uint32_t sb = smem_u32(sm);
    const int tid  = threadIdx.x;
    const int lane = tid & 31;
    const int warp = tid >> 5;
    const int warp_m = warp & 3;
    const int warp_n = warp >> 2;
    const int mt = blockIdx.x % M_TILES;
    const int nt = blockIdx.x / M_TILES;

    const uint8_t* ag = g_xbuf + (size_t)(mt * K_TILES) * TILE_BYTES;
    const uint8_t* bg = g_wbuf + (size_t)(nt * K_TILES) * TILE_BYTES;

    // per-thread cp.async slice: 4x16B from A tile + 4x16B from B tile
    const uint32_t cp_off = (uint32_t)tid * 64;

    // prologue: stages 0 and 1
#pragma unroll
    for (int s = 0; s < 2; s++) {
        uint32_t dA = sb + s * STAGE_BYTES + cp_off;
        uint32_t dB = dA + TILE_BYTES;
        const uint8_t* srcA = ag + (size_t)s * TILE_BYTES + cp_off;
        const uint8_t* srcB = bg + (size_t)s * TILE_BYTES + cp_off;
#pragma unroll
        for (int j = 0; j < 4; j++) {
            cpasync16(dA + j * 16, srcA + j * 16);
            cpasync16(dB + j * 16, srcB + j * 16);
        }
        cp_commit();
    }

    // per-lane ldmatrix address components (SW128: swz(r*128+c) = r*128 + (c ^ ((r&7)<<4)))
    const int a_row = warp_m * 32 + (lane & 15);          // + 16*mtile
    const uint32_t a_xor = (uint32_t)((a_row & 7) << 4);
    const uint32_t a_cb  = (uint32_t)((lane >> 4) << 4);  // 0 or 16
    const int b_row = warp_n * 64 + (lane & 7) + ((lane >> 4) << 3);  // + 16*p
    const uint32_t b_xor = (uint32_t)((b_row & 7) << 4);
    const uint32_t b_cb  = (uint32_t)((lane & 8) << 1);   // 0 or 16

    float acc[2][8][4];
#pragma unroll
    for (int i = 0; i < 2; i++)
#pragma unroll
        for (int j = 0; j < 8; j++)
#pragma unroll
            for (int q = 0; q < 4; q++) acc[i][j][q] = 0.f;

#pragma unroll 1
    for (int kt = 0; kt < K_TILES; kt++) {
        cp_wait1();
        __syncthreads();

        // issue stage kt+2
        if (kt + 2 < K_TILES) {
            int s = (kt + 2) % STAGES;
            uint32_t dA = sb + s * STAGE_BYTES + cp_off;
            uint32_t dB = dA + TILE_BYTES;
            const uint8_t* srcA = ag + (size_t)(kt + 2) * TILE_BYTES + cp_off;
            const uint8_t* srcB = bg + (size_t)(kt + 2) * TILE_BYTES + cp_off;
#pragma unroll
            for (int j = 0; j < 4; j++) {
                cpasync16(dA + j * 16, srcA + j * 16);
                cpasync16(dB + j * 16, srcB + j * 16);
            }
        }
        cp_commit();

        // compute stage kt
        uint32_t sA = sb + (kt % STAGES) * STAGE_BYTES;
        uint32_t sB = sA + TILE_BYTES;
#pragma unroll
        for (int k16 = 0; k16 < 4; k16++) {
            uint32_t kc = (uint32_t)(k16 * 32);
            uint32_t a[2][4];
#pragma unroll
            for (int mtile = 0; mtile < 2; mtile++) {
                uint32_t addr = sA + (uint32_t)(a_row + 16 * mtile) * 128 + ((kc + a_cb) ^ a_xor);
                ldsm4(a[mtile], addr);
            }
#pragma unroll
            for (int p = 0; p < 4; p++) {
                uint32_t bb[4];
                uint32_t addr = sB + (uint32_t)(b_row + 16 * p) * 128 + ((kc + b_cb) ^ b_xor);
                ldsm4(bb, addr);
                mma16816(acc[0][2 * p + 0], a[0], bb + 0);
                mma16816(acc[0][2 * p + 1], a[0], bb + 2);
                mma16816(acc[1][2 * p + 0], a[1], bb + 0);
                mma16816(acc[1][2 * p + 1], a[1], bb + 2);
            }
        }
    }

    // epilogue: plain accumulator stores (scale/zero already folded into W)
    const int m_lo = mt * BM + warp_m * 32 + (lane >> 2);
    const int n_lo = nt * BN + warp_n * 64 + 2 * (lane & 3);
#pragma unroll
    for (int mtile = 0; mtile < 2; mtile++) {
        int m0 = m_lo + 16 * mtile;
        float* o0 = out + (size_t)m0 * OUT_F + n_lo;
        float* o1 = o0 + (size_t)8 * OUT_F;
#pragma unroll
        for (int p = 0; p < 8; p++) {
            float2 v0, v1;
            v0.x = acc[mtile][p][0];
            v0.y = acc[mtile][p][1];
            v1.x = acc[mtile][p][2];
            v1.y = acc[mtile][p][3];
            *(float2*)(o0 + 8 * p) = v0;
            *(float2*)(o1 + 8 * p) = v1;
        }
    }
}

// ---------------- launch ----------------
extern "C" void kernel_launch(void* const* d_in, const int* in_sizes, int n_in,
                              void* d_out, int out_size) {
    const float* x     = (const float*)d_in[0];
    const int*   wpack = (const int*)d_in[1];   // uint8 promoted to int32 by harness
    const float* scale = (const float*)d_in[2];
    const float* zero  = (const float*)d_in[3];
    float*       out   = (float*)d_out;

    cudaFuncSetAttribute(gemm_kernel, cudaFuncAttributeMaxDynamicSharedMemorySize, SMEM_BYTES);

    convert_x_kernel<<<M_TILES * K_TILES, 128>>>(x);
    dequant_w_kernel<<<N_TILES * K_TILES, 128>>>(wpack, scale, zero);
    gemm_kernel<<<M_TILES * N_TILES, 256, SMEM_BYTES>>>(out);
}